// round 1
// baseline (speedup 1.0000x reference)
#include <cuda_runtime.h>
#include <cstdint>

#define D 128
#define P 8
#define NMAX 100000
#define LMAX 3

// Scratch (device globals — no allocation allowed)
__device__ float g_ax[(size_t)NMAX * D];       // SpMM output per layer
__device__ float g_hA[(size_t)NMAX * D];       // ping
__device__ float g_hB[(size_t)NMAX * D];       // pong
__device__ int   g_row_ptr[NMAX + 1];
__device__ float g_wwT[LMAX * D * D];          // [l][i][o]  (transposed effective weight)

// ---------------------------------------------------------------------------
// row_ptr[r] = lower_bound(edge_row, r)  (edge_row sorted ascending)
// ---------------------------------------------------------------------------
__global__ void build_row_ptr_k(const int* __restrict__ edge_row, int E, int N) {
    int r = blockIdx.x * blockDim.x + threadIdx.x;
    if (r > N) return;
    int lo = 0, hi = E;
    while (lo < hi) {
        int mid = (lo + hi) >> 1;
        if (edge_row[mid] < r) lo = mid + 1; else hi = mid;
    }
    g_row_ptr[r] = lo;
}

// ---------------------------------------------------------------------------
// wwT[l][i][o] = sum_p sp[l][o][i][p] * softmax(lw[l])[p]
// grid.x = L*D (l,i), block = D threads (o)
// ---------------------------------------------------------------------------
__global__ void build_weights_k(const float* __restrict__ sp, const float* __restrict__ lw) {
    int l = blockIdx.x >> 7;
    int i = blockIdx.x & 127;
    int o = threadIdx.x;

    float w[P];
    float m = -1e30f;
#pragma unroll
    for (int p = 0; p < P; p++) { w[p] = lw[l * P + p]; m = fmaxf(m, w[p]); }
    float s = 0.f;
#pragma unroll
    for (int p = 0; p < P; p++) { w[p] = expf(w[p] - m); s += w[p]; }
    float inv = 1.f / s;

    const float* base = sp + (((size_t)l * D + o) * D + i) * P;
    float acc = 0.f;
#pragma unroll
    for (int p = 0; p < P; p++) acc = fmaf(base[p], w[p] * inv, acc);
    g_wwT[((size_t)l * D + i) * D + o] = acc;
}

// ---------------------------------------------------------------------------
// SpMM: one warp per row. ax[r,:] = sum_{e in row r} val[e] * h[col[e],:]
// Each lane owns 4 consecutive floats via float4 (coalesced 512B per edge).
// ---------------------------------------------------------------------------
__global__ void spmm_k(const int* __restrict__ col, const float* __restrict__ val,
                       const float* __restrict__ h, int N) {
    int warp = (int)((blockIdx.x * blockDim.x + threadIdx.x) >> 5);
    int lane = threadIdx.x & 31;
    if (warp >= N) return;
    int s = g_row_ptr[warp];
    int e = g_row_ptr[warp + 1];
    float4 acc = make_float4(0.f, 0.f, 0.f, 0.f);
    for (int k = s; k < e; k++) {
        int c = __ldg(col + k);
        float v = __ldg(val + k);
        float4 hv = __ldg(((const float4*)(h + (size_t)c * D)) + lane);
        acc.x = fmaf(v, hv.x, acc.x);
        acc.y = fmaf(v, hv.y, acc.y);
        acc.z = fmaf(v, hv.z, acc.z);
        acc.w = fmaf(v, hv.w, acc.w);
    }
    ((float4*)(g_ax + (size_t)warp * D))[lane] = acc;
}

// ---------------------------------------------------------------------------
// GEMM: C[N x 128] = A[N x 128] * B  where B is wwT laid out [k][o]
// (i.e. C[n][o] = sum_k A[n][k] * B[k][o]). Block tile 128x128, 256 threads,
// 8x8 register micro-tiles, 16-wide k-chunks, A staged transposed in smem.
// ---------------------------------------------------------------------------
template <bool RELU>
__global__ __launch_bounds__(256) void gemm_k(const float* __restrict__ A,
                                              const float* __restrict__ B,
                                              float* __restrict__ C, int N) {
    __shared__ float As[16][128];   // [k][row]
    __shared__ float Bs[16][128];   // [k][col]

    const int row0 = blockIdx.x * 128;
    const int tid  = threadIdx.x;
    const int tx   = tid & 15;      // col group (8 cols)
    const int ty   = tid >> 4;      // row group (8 rows)

    const int arow = tid >> 1;             // row this thread stages (two threads/row)
    const int akh  = (tid & 1) * 8;        // which 8 k's
    const bool arow_ok = (row0 + arow) < N;

    float acc[8][8];
#pragma unroll
    for (int i = 0; i < 8; i++)
#pragma unroll
        for (int j = 0; j < 8; j++) acc[i][j] = 0.f;

    for (int kk = 0; kk < 128; kk += 16) {
        // stage B chunk (16 x 128), straight copy, coalesced float4
        const float4* B4 = (const float4*)(B + kk * 128);
        ((float4*)Bs)[tid]       = B4[tid];
        ((float4*)Bs)[tid + 256] = B4[tid + 256];

        // stage A chunk transposed: As[k][row]
        float4 v0 = make_float4(0.f, 0.f, 0.f, 0.f), v1 = v0;
        if (arow_ok) {
            const float4* A4 = (const float4*)(A + (size_t)(row0 + arow) * 128 + kk + akh);
            v0 = A4[0];
            v1 = A4[1];
        }
        As[akh + 0][arow] = v0.x; As[akh + 1][arow] = v0.y;
        As[akh + 2][arow] = v0.z; As[akh + 3][arow] = v0.w;
        As[akh + 4][arow] = v1.x; As[akh + 5][arow] = v1.y;
        As[akh + 6][arow] = v1.z; As[akh + 7][arow] = v1.w;
        __syncthreads();

#pragma unroll
        for (int k = 0; k < 16; k++) {
            float4 a0 = *(const float4*)&As[k][ty * 8];
            float4 a1 = *(const float4*)&As[k][ty * 8 + 4];
            float4 b0 = *(const float4*)&Bs[k][tx * 8];
            float4 b1 = *(const float4*)&Bs[k][tx * 8 + 4];
            float a[8] = {a0.x, a0.y, a0.z, a0.w, a1.x, a1.y, a1.z, a1.w};
            float b[8] = {b0.x, b0.y, b0.z, b0.w, b1.x, b1.y, b1.z, b1.w};
#pragma unroll
            for (int i = 0; i < 8; i++)
#pragma unroll
                for (int j = 0; j < 8; j++)
                    acc[i][j] = fmaf(a[i], b[j], acc[i][j]);
        }
        __syncthreads();
    }

#pragma unroll
    for (int i = 0; i < 8; i++) {
        int r = row0 + ty * 8 + i;
        if (r < N) {
            float4 o0, o1;
            float* src = &acc[i][0];
            if (RELU) {
#pragma unroll
                for (int j = 0; j < 8; j++) src[j] = fmaxf(src[j], 0.f);
            }
            o0 = make_float4(src[0], src[1], src[2], src[3]);
            o1 = make_float4(src[4], src[5], src[6], src[7]);
            float4* Crow = (float4*)(C + (size_t)r * 128 + tx * 8);
            Crow[0] = o0;
            Crow[1] = o1;
        }
    }
}

// ---------------------------------------------------------------------------
extern "C" void kernel_launch(void* const* d_in, const int* in_sizes, int n_in,
                              void* d_out, int out_size) {
    const int*   edge_row  = (const int*)d_in[0];
    const int*   edge_col  = (const int*)d_in[1];
    const float* edge_vals = (const float*)d_in[2];
    const float* x         = (const float*)d_in[3];
    const float* sp        = (const float*)d_in[4];
    const float* lw        = (const float*)d_in[5];
    float*       out       = (float*)d_out;

    const int E = in_sizes[0];
    const int N = in_sizes[3] / D;
    const int L = in_sizes[5] / P;

    void *p_ax, *p_hA, *p_hB, *p_ww;
    cudaGetSymbolAddress(&p_ax, g_ax);
    cudaGetSymbolAddress(&p_hA, g_hA);
    cudaGetSymbolAddress(&p_hB, g_hB);
    cudaGetSymbolAddress(&p_ww, g_wwT);

    build_row_ptr_k<<<(N + 256) / 256, 256>>>(edge_row, E, N);
    build_weights_k<<<L * D, D>>>(sp, lw);

    float* bufs[2] = {(float*)p_hA, (float*)p_hB};
    const float* hin = x;
    const int gemm_blocks = (N + 127) / 128;
    const int spmm_blocks = (N + 7) / 8;   // 8 warps (rows) per 256-thread block

    for (int l = 0; l < L; l++) {
        spmm_k<<<spmm_blocks, 256>>>(edge_col, edge_vals, hin, N);
        const float* Bm = (const float*)p_ww + (size_t)l * D * D;
        float* Cout = (l == L - 1) ? out : bufs[l & 1];
        if (l < L - 1)
            gemm_k<true><<<gemm_blocks, 256>>>((const float*)p_ax, Bm, Cout, N);
        else
            gemm_k<false><<<gemm_blocks, 256>>>((const float*)p_ax, Bm, Cout, N);
        hin = Cout;
    }
}

// round 2
// speedup vs baseline: 1.2313x; 1.2313x over previous
#include <cuda_runtime.h>
#include <cstdint>

#define D 128
#define P 8
#define NMAX 100000
#define LMAX 3
#define BS_STRIDE 136   // smem B row stride (floats): banks for (t,g) frag reads all distinct

// Scratch (device globals — no allocation allowed)
__device__ float g_ax[(size_t)NMAX * D];       // SpMM output per layer
__device__ float g_hA[(size_t)NMAX * D];       // ping
__device__ float g_hB[(size_t)NMAX * D];       // pong
__device__ int   g_row_ptr[NMAX + 1];
__device__ float g_wwT[LMAX * D * D];          // [l][k][o] (transposed effective weight)

// ---------------------------------------------------------------------------
// row_ptr[r] = lower_bound(edge_row, r)  (edge_row sorted ascending)
// ---------------------------------------------------------------------------
__global__ void build_row_ptr_k(const int* __restrict__ edge_row, int E, int N) {
    int r = blockIdx.x * blockDim.x + threadIdx.x;
    if (r > N) return;
    int lo = 0, hi = E;
    while (lo < hi) {
        int mid = (lo + hi) >> 1;
        if (edge_row[mid] < r) lo = mid + 1; else hi = mid;
    }
    g_row_ptr[r] = lo;
}

// ---------------------------------------------------------------------------
// wwT[l][k][o] = sum_p sp[l][o][k][p] * softmax(lw[l])[p]
// ---------------------------------------------------------------------------
__global__ void build_weights_k(const float* __restrict__ sp, const float* __restrict__ lw) {
    int l = blockIdx.x >> 7;
    int i = blockIdx.x & 127;
    int o = threadIdx.x;

    float w[P];
    float m = -1e30f;
#pragma unroll
    for (int p = 0; p < P; p++) { w[p] = lw[l * P + p]; m = fmaxf(m, w[p]); }
    float s = 0.f;
#pragma unroll
    for (int p = 0; p < P; p++) { w[p] = expf(w[p] - m); s += w[p]; }
    float inv = 1.f / s;

    const float* base = sp + (((size_t)l * D + o) * D + i) * P;
    float acc = 0.f;
#pragma unroll
    for (int p = 0; p < P; p++) acc = fmaf(base[p], w[p] * inv, acc);
    g_wwT[((size_t)l * D + i) * D + o] = acc;
}

// ---------------------------------------------------------------------------
// SpMM: one warp per row (at L2-gather floor, leave as is)
// ---------------------------------------------------------------------------
__global__ void spmm_k(const int* __restrict__ col, const float* __restrict__ val,
                       const float* __restrict__ h, int N) {
    int warp = (int)((blockIdx.x * blockDim.x + threadIdx.x) >> 5);
    int lane = threadIdx.x & 31;
    if (warp >= N) return;
    int s = g_row_ptr[warp];
    int e = g_row_ptr[warp + 1];
    float4 acc = make_float4(0.f, 0.f, 0.f, 0.f);
    for (int k = s; k < e; k++) {
        int c = __ldg(col + k);
        float v = __ldg(val + k);
        float4 hv = __ldg(((const float4*)(h + (size_t)c * D)) + lane);
        acc.x = fmaf(v, hv.x, acc.x);
        acc.y = fmaf(v, hv.y, acc.y);
        acc.z = fmaf(v, hv.z, acc.z);
        acc.w = fmaf(v, hv.w, acc.w);
    }
    ((float4*)(g_ax + (size_t)warp * D))[lane] = acc;
}

// ---------------------------------------------------------------------------
// Tensor-core GEMM (3xTF32): C[N x 128] = A[N x 128] * B[128 x 128]
// B layout [k][o] row-major. Block = 256 threads (8 warps), 128 rows/block.
// Each warp: 16 rows x 128 cols, k-loop in chunks of 8 via mma.m16n8k8.tf32.
// ---------------------------------------------------------------------------
__device__ __forceinline__ void mma_tf32(float (&d)[4],
                                         uint32_t a0, uint32_t a1, uint32_t a2, uint32_t a3,
                                         uint32_t b0, uint32_t b1) {
    asm volatile(
        "mma.sync.aligned.m16n8k8.row.col.f32.tf32.tf32.f32 "
        "{%0,%1,%2,%3},{%4,%5,%6,%7},{%8,%9},{%0,%1,%2,%3};"
        : "+f"(d[0]), "+f"(d[1]), "+f"(d[2]), "+f"(d[3])
        : "r"(a0), "r"(a1), "r"(a2), "r"(a3), "r"(b0), "r"(b1));
}

__device__ __forceinline__ void split_tf32(float v, uint32_t& hi, uint32_t& lo) {
    uint32_t h = __float_as_uint(v) & 0xffffe000u;
    hi = h;
    lo = __float_as_uint(v - __uint_as_float(h));
}

template <bool RELU>
__global__ __launch_bounds__(256) void gemm_tc(const float* __restrict__ A,
                                               const float* __restrict__ B,
                                               float* __restrict__ C, int N) {
    extern __shared__ float Bs[];   // [128][BS_STRIDE]

    const int tid = threadIdx.x;

    // stage B (128x128) into smem, coalesced float4 reads
#pragma unroll
    for (int i = tid; i < 128 * 32; i += 256) {
        int row = i >> 5;
        int c4  = (i & 31) << 2;
        float4 v = __ldg((const float4*)(B + row * 128 + c4));
        float* dst = &Bs[row * BS_STRIDE + c4];
        dst[0] = v.x; dst[1] = v.y; dst[2] = v.z; dst[3] = v.w;
    }
    __syncthreads();

    const int warp = tid >> 5;
    const int lane = tid & 31;
    const int g = lane >> 2;      // group (row within frag / n within B frag)
    const int t = lane & 3;       // thread-in-group (k within frag)

    const int r0 = blockIdx.x * 128 + warp * 16;
    const int rA = r0 + g;
    const int rB = r0 + g + 8;
    const bool okA = rA < N;
    const bool okB = rB < N;

    const float* pA  = A + (size_t)rA * 128;
    const float* pA2 = A + (size_t)rB * 128;

    float acc[16][4];
#pragma unroll
    for (int j = 0; j < 16; j++)
#pragma unroll
        for (int q = 0; q < 4; q++) acc[j][q] = 0.f;

#pragma unroll
    for (int kk = 0; kk < 128; kk += 8) {
        float a0f = okA ? __ldg(pA  + kk + t)     : 0.f;
        float a2f = okA ? __ldg(pA  + kk + t + 4) : 0.f;
        float a1f = okB ? __ldg(pA2 + kk + t)     : 0.f;
        float a3f = okB ? __ldg(pA2 + kk + t + 4) : 0.f;

        uint32_t a0h, a0l, a1h, a1l, a2h, a2l, a3h, a3l;
        split_tf32(a0f, a0h, a0l);
        split_tf32(a1f, a1h, a1l);
        split_tf32(a2f, a2h, a2l);
        split_tf32(a3f, a3h, a3l);

        const float* brow0 = &Bs[(kk + t) * BS_STRIDE + g];
        const float* brow1 = &Bs[(kk + t + 4) * BS_STRIDE + g];

#pragma unroll
        for (int j = 0; j < 16; j++) {
            float b0f = brow0[j * 8];
            float b1f = brow1[j * 8];
            uint32_t b0h, b0l, b1h, b1l;
            split_tf32(b0f, b0h, b0l);
            split_tf32(b1f, b1h, b1l);
            // 3xTF32: small terms first
            mma_tf32(acc[j], a0l, a1l, a2l, a3l, b0h, b1h);
            mma_tf32(acc[j], a0h, a1h, a2h, a3h, b0l, b1l);
            mma_tf32(acc[j], a0h, a1h, a2h, a3h, b0h, b1h);
        }
    }

    // epilogue: c0,c1 -> row rA cols (j*8+2t, +1); c2,c3 -> row rB
#pragma unroll
    for (int j = 0; j < 16; j++) {
        float v0 = acc[j][0], v1 = acc[j][1], v2 = acc[j][2], v3 = acc[j][3];
        if (RELU) {
            v0 = fmaxf(v0, 0.f); v1 = fmaxf(v1, 0.f);
            v2 = fmaxf(v2, 0.f); v3 = fmaxf(v3, 0.f);
        }
        int c = j * 8 + 2 * t;
        if (okA) *(float2*)(C + (size_t)rA * 128 + c) = make_float2(v0, v1);
        if (okB) *(float2*)(C + (size_t)rB * 128 + c) = make_float2(v2, v3);
    }
}

// ---------------------------------------------------------------------------
extern "C" void kernel_launch(void* const* d_in, const int* in_sizes, int n_in,
                              void* d_out, int out_size) {
    const int*   edge_row  = (const int*)d_in[0];
    const int*   edge_col  = (const int*)d_in[1];
    const float* edge_vals = (const float*)d_in[2];
    const float* x         = (const float*)d_in[3];
    const float* sp        = (const float*)d_in[4];
    const float* lw        = (const float*)d_in[5];
    float*       out       = (float*)d_out;

    const int E = in_sizes[0];
    const int N = in_sizes[3] / D;
    const int L = in_sizes[5] / P;

    void *p_ax, *p_hA, *p_hB, *p_ww;
    cudaGetSymbolAddress(&p_ax, g_ax);
    cudaGetSymbolAddress(&p_hA, g_hA);
    cudaGetSymbolAddress(&p_hB, g_hB);
    cudaGetSymbolAddress(&p_ww, g_wwT);

    const int smem_bytes = 128 * BS_STRIDE * 4;   // 69632
    cudaFuncSetAttribute(gemm_tc<true>,  cudaFuncAttributeMaxDynamicSharedMemorySize, smem_bytes);
    cudaFuncSetAttribute(gemm_tc<false>, cudaFuncAttributeMaxDynamicSharedMemorySize, smem_bytes);

    build_row_ptr_k<<<(N + 256) / 256, 256>>>(edge_row, E, N);
    build_weights_k<<<L * D, D>>>(sp, lw);

    float* bufs[2] = {(float*)p_hA, (float*)p_hB};
    const float* hin = x;
    const int gemm_blocks = (N + 127) / 128;
    const int spmm_blocks = (N + 7) / 8;

    for (int l = 0; l < L; l++) {
        spmm_k<<<spmm_blocks, 256>>>(edge_col, edge_vals, hin, N);
        const float* Bm = (const float*)p_ww + (size_t)l * D * D;
        float* Cout = (l == L - 1) ? out : bufs[l & 1];
        if (l < L - 1)
            gemm_tc<true><<<gemm_blocks, 256, smem_bytes>>>((const float*)p_ax, Bm, Cout, N);
        else
            gemm_tc<false><<<gemm_blocks, 256, smem_bytes>>>((const float*)p_ax, Bm, Cout, N);
        hin = Cout;
    }
}